// round 17
// baseline (speedup 1.0000x reference)
#include <cuda_runtime.h>

#define HW      256
#define NB      8
#define CH      64
#define HWHW    65536
#define F4ROW   64        // HW/4
#define F4IMG   16384     // HWHW/4
#define THREADS 512
#define GRID    296
#define NUNITS  2048
#define ITERS   7         // ceil(2048/296)

__device__ __forceinline__ void acc_abs(float4& s, const float4 a) {
    s.x += fabsf(a.x); s.y += fabsf(a.y); s.z += fabsf(a.z); s.w += fabsf(a.w);
}

__global__ void __launch_bounds__(THREADS, 2)
k_fused(const float* __restrict__ x1, const float* __restrict__ x2,
        const float* __restrict__ w,  const float* __restrict__ bias,
        float* __restrict__ out) {
    __shared__ float4 part[3][2][4][64];     // 24 KB, within-iteration
    __shared__ float  nrm[3][2][HW];         //  6 KB, within-iteration
    __shared__ float  f1s[2][HW], f2s[2][HW];//  4 KB, double-buffered factors

    const int bid = blockIdx.x;
    const int t   = threadIdx.x;
    const int arr  = t >> 8;                 // 0: x1, 1: x2   (norm role)
    const int grp  = (t >> 6) & 3;           // 16-channel group
    const int quad = t & 63;                 // float4 quad
    const int chb  = t >> 6;                 // blend: base channel 0..7
    const int qq   = t & 63;                 // blend: quad

    const float4* xa = (const float4*)(arr ? x2 : x1);

    for (int wi = 0; wi <= ITERS; ++wi) {
        const int  uL  = bid + wi * GRID;
        const bool doL = (wi < ITERS) && (uL < NUNITS);
        const int  uB  = bid + (wi - 1) * GRID;
        const bool doB = (wi >= 1) && (uB < NUNITS);

        // ---------- phase 1: ALL memory work, no barriers ----------
        float4 a0 = make_float4(0.f,0.f,0.f,0.f);
        float4 a1 = a0, a2 = a0;
        if (doL) {
            const int bbL = uL >> 8, rL = uL & 255;
            const float4* px = xa + (size_t)bbL * CH * F4IMG
                             + (size_t)(grp * 16) * F4IMG + quad;
            const bool vA = (rL > 0), vB = (rL < HW - 1);
            const float4* pA = px + (size_t)(vA ? rL - 1 : 0) * F4ROW;
            const float4* pB = px + (size_t)(vB ? rL + 1 : 0) * F4ROW;
            const float4* pC = px + (size_t)rL * F4ROW;
#pragma unroll
            for (int j = 0; j < 16; ++j) {
                if (vA) acc_abs(a0, pA[(size_t)j * F4IMG]);
                if (vB) acc_abs(a2, pB[(size_t)j * F4IMG]);
                acc_abs(a1, pC[(size_t)j * F4IMG]);
            }
        }
        if (doB) {
            const int bbB = uB >> 8, rB = uB & 255;
            const int fb  = (wi - 1) & 1;
            const float4 F1 = ((const float4*)f1s[fb])[qq];
            const float4 F2 = ((const float4*)f2s[fb])[qq];
            const size_t base = (size_t)bbB * CH * F4IMG
                              + (size_t)chb * F4IMG + (size_t)rB * F4ROW + qq;
            const float4* p1 = (const float4*)x1 + base;
            const float4* p2 = (const float4*)x2 + base;
            float4*       po = (float4*)out + base;
#pragma unroll
            for (int i = 0; i < 8; ++i) {    // channels chb, chb+8, ...
                const size_t off = (size_t)i * 8 * F4IMG;
                const float4 a = __ldcs(p1 + off);
                const float4 v = __ldcs(p2 + off);
                float4 o;
                o.x = a.x * F1.x + v.x * F2.x;
                o.y = a.y * F1.y + v.y * F2.y;
                o.z = a.z * F1.z + v.z * F2.z;
                o.w = a.w * F1.w + v.w * F2.w;
                __stcs(po + off, o);
            }
        }
        if (doL) {
            part[0][arr][grp][quad] = a0;
            part[1][arr][grp][quad] = a1;
            part[2][arr][grp][quad] = a2;
        }
        __syncthreads();

        // ---------- phase 2: reduce partials -> nrm ----------
        if (doL && t < 384) {
            const int dr = t >> 7, ar = (t >> 6) & 1, q2 = t & 63;
            float4 s = part[dr][ar][0][q2];
#pragma unroll
            for (int k = 1; k < 4; ++k) {
                const float4 a = part[dr][ar][k][q2];
                s.x += a.x; s.y += a.y; s.z += a.z; s.w += a.w;
            }
            ((float4*)nrm[dr][ar])[q2] = s;
        }
        __syncthreads();

        // ---------- phase 3: conv -> factors (buffer wi&1) ----------
        if (doL && t < HW) {
            const int rL = uL & 255;
            float c1 = __ldg(bias), c2 = c1;
#pragma unroll
            for (int dr = 0; dr < 3; ++dr) {
                const int rr = rL + dr - 1;
                if (rr < 0 || rr >= HW) continue;   // matches zero-padded nrm
                const float* n1r = nrm[dr][0];
                const float* n2r = nrm[dr][1];
#pragma unroll
                for (int dj = 0; dj < 3; ++dj) {
                    const int cc = t + dj - 1;
                    if (cc < 0 || cc >= HW) continue;
                    const float ww = __ldg(w + dr * 3 + dj);
                    c1 += ww * n1r[cc];
                    c2 += ww * n2r[cc];
                }
            }
            const float rd = 1.0f / (c1 + c2);
            f1s[wi & 1][t] = c1 * rd;
            f2s[wi & 1][t] = c2 * rd;
        }
        __syncthreads();
    }
}

extern "C" void kernel_launch(void* const* d_in, const int* in_sizes, int n_in,
                              void* d_out, int out_size) {
    const float* x1   = (const float*)d_in[0];
    const float* x2   = (const float*)d_in[1];
    const float* w    = (const float*)d_in[2];
    const float* bias = (const float*)d_in[3];
    float*       out  = (float*)d_out;

    k_fused<<<GRID, THREADS>>>(x1, x2, w, bias, out);
}